// round 11
// baseline (speedup 1.0000x reference)
#include <cuda_runtime.h>
#include <cstdint>

// SparseAdam via per-vocab linked lists + single fused streaming pass.
//
// Inputs: 0 idx i32[N], 1 grad f32[N,128], 2 emb f32[V,128], 3 step f32[V],
//         4 mem f32[V,128], 5 pow f32[V,128]
// Output: new_emb[V,128] | new_step[V] | new_mem[V,128] | new_pow[V,128]
//
// 3 graph nodes:
//   memset(head=-1) -> link_k (next[i]=atomicExch(&head[idx[i]],i)) ->
//   update_k (walk list per vocab row; ~3.6 GB streaming floor).

#define DD 128
#define MAXE (1 << 21)

__device__ int g_head[MAXE];
__device__ int g_next[MAXE];

// ---------------------------------------------------------------------------
// Build linked lists. next[] stores are coalesced (thread owns 4 consecutive i).
// ---------------------------------------------------------------------------
__global__ void link_k(const int* __restrict__ idx, int N) {
    const int n4 = N >> 2;
    const int stride = gridDim.x * blockDim.x;
    const int4* idx4 = (const int4*)idx;
    for (int i = blockIdx.x * blockDim.x + threadIdx.x; i < n4; i += stride) {
        int4 v = __ldg(idx4 + i);
        const int b = i << 2;
        int4 nx;
        nx.x = atomicExch(&g_head[v.x], b);
        nx.y = atomicExch(&g_head[v.y], b + 1);
        nx.z = atomicExch(&g_head[v.z], b + 2);
        nx.w = atomicExch(&g_head[v.w], b + 3);
        ((int4*)g_next)[i] = nx;
    }
    for (int i = (n4 << 2) + blockIdx.x * blockDim.x + threadIdx.x; i < N; i += stride)
        g_next[i] = atomicExch(&g_head[__ldg(idx + i)], i);
}

// ---------------------------------------------------------------------------
// Fused gather + Adam update. One warp per vocab row, float4 per lane.
// Walk the row's linked list; next-pointer and grad loads issue back-to-back.
// ---------------------------------------------------------------------------
__global__ void __launch_bounds__(256, 7)
sadam_update_k(const float4* __restrict__ grad,
               const float4* __restrict__ emb,
               const float*  __restrict__ step_in,
               const float4* __restrict__ mem,
               const float4* __restrict__ pw,
               float4* __restrict__ out_emb,
               float*  __restrict__ out_step,
               float4* __restrict__ out_mem,
               float4* __restrict__ out_pow,
               int V) {
    const long gtid = (long)blockIdx.x * blockDim.x + threadIdx.x;
    const long row  = gtid >> 5;
    if (row >= V) return;
    const int  lane = (int)(gtid & 31);
    const long i4   = row * (DD / 4) + lane;

    // Start the dependent gather chain first.
    int r = __ldg(&g_head[row]);          // -1 if untouched (lane-uniform)

    // Independent streams overlap the chain.
    float4 e = __ldcs(emb + i4);
    float4 m = __ldcs(mem + i4);
    float4 p = __ldcs(pw  + i4);
    const float st = __ldg(step_in + row);

    float4 ne, nm, np;
    float  nstep;

    if (r >= 0) {
        float4 gs = make_float4(0.f, 0.f, 0.f, 0.f);
        int cnt = 0;
        do {
            const int rn = __ldg(&g_next[r]);            // issues with grad load
            float4 g = __ldcs(grad + (long)r * (DD / 4) + lane);
            gs.x += g.x; gs.y += g.y; gs.z += g.z; gs.w += g.w;
            cnt++;
            r = rn;
        } while (r >= 0);

        nstep = st + 1.f;
        const float inv = 1.f / (float)cnt;
        const float d1 = 1.f - exp2f(nstep * -0.15200309344504997f);   // 1-0.9^s
        const float d2 = 1.f - exp2f(nstep * -0.0014434169010128458f); // 1-0.999^s
        const float c1  = 0.001f / d1;
        const float id2 = 1.f / d2;

        #define ADAM1(GS, M, P, E, NM, NP, NE)                       \
        {                                                             \
            float g = (GS) * inv;                                     \
            NM = 0.9f * (M) + 0.1f * g;                               \
            NP = 0.999f * (P) + 0.001f * (g * g);                     \
            float stdv = c1 * NM / (sqrtf(NP * id2) + 1e-8f);         \
            NE = (E) - stdv;                                          \
        }
        ADAM1(gs.x, m.x, p.x, e.x, nm.x, np.x, ne.x)
        ADAM1(gs.y, m.y, p.y, e.y, nm.y, np.y, ne.y)
        ADAM1(gs.z, m.z, p.z, e.z, nm.z, np.z, ne.z)
        ADAM1(gs.w, m.w, p.w, e.w, nm.w, np.w, ne.w)
        #undef ADAM1
    } else {
        nstep = st;
        ne = e; nm = m; np = p;
    }

    __stcs(out_emb + i4, ne);
    __stcs(out_mem + i4, nm);
    __stcs(out_pow + i4, np);
    if (lane == 0) out_step[row] = nstep;
}

// ---------------------------------------------------------------------------
extern "C" void kernel_launch(void* const* d_in, const int* in_sizes, int n_in,
                              void* d_out, int out_size) {
    const int*   idx  = (const int*)  d_in[0];
    const float* grad = (const float*)d_in[1];
    const float* emb  = (const float*)d_in[2];
    const float* step = (const float*)d_in[3];
    const float* mem  = (const float*)d_in[4];
    const float* pw   = (const float*)d_in[5];

    const int N = in_sizes[0];
    const int V = in_sizes[3];

    float* out      = (float*)d_out;
    float* out_emb  = out;
    float* out_step = out_emb + (long)V * DD;
    float* out_mem  = out_step + V;
    float* out_pow  = out_mem + (long)V * DD;

    // head = -1 everywhere (0xFF bytes).
    void* head_ptr = nullptr;
    cudaGetSymbolAddress(&head_ptr, g_head);
    cudaMemsetAsync(head_ptr, 0xFF, (size_t)V * sizeof(int));

    link_k<<<592, 256>>>(idx, N);

    {
        const long threads = (long)V * 32;
        const int  blocks  = (int)((threads + 255) / 256);
        sadam_update_k<<<blocks, 256>>>((const float4*)grad, (const float4*)emb,
                                        step, (const float4*)mem, (const float4*)pw,
                                        (float4*)out_emb, out_step,
                                        (float4*)out_mem, (float4*)out_pow, V);
    }
}

// round 15
// speedup vs baseline: 1.0118x; 1.0118x over previous
#include <cuda_runtime.h>
#include <cstdint>

// SparseAdam via per-vocab linked lists + single fused streaming pass.
//
// Inputs: 0 idx i32[N], 1 grad f32[N,128], 2 emb f32[V,128], 3 step f32[V],
//         4 mem f32[V,128], 5 pow f32[V,128]
// Output: new_emb[V,128] | new_step[V] | new_mem[V,128] | new_pow[V,128]
//
// 2 graph nodes:
//   link_k   : next[i] = atomicExch(&head[idx[i]], i+1) - 1
//   update_k : walk list per vocab row (3.6 GB streaming floor), then reset
//              head[row] = 0 so the graph replays against a clean index.
// head uses sentinel 0 (= empty, zero-init at module load); stored value is
// rowid+1. update_k self-restores head, so no memset node is needed.

#define DD 128
#define MAXE (1 << 21)

__device__ int g_head[MAXE];   // zero-initialized; 0 = empty, else rowid+1
__device__ int g_next[MAXE];

// ---------------------------------------------------------------------------
// Build linked lists. next[] stores are coalesced (thread owns 4 consecutive i).
// ---------------------------------------------------------------------------
__global__ void link_k(const int* __restrict__ idx, int N) {
    const int n4 = N >> 2;
    const int stride = gridDim.x * blockDim.x;
    const int4* idx4 = (const int4*)idx;
    for (int i = blockIdx.x * blockDim.x + threadIdx.x; i < n4; i += stride) {
        int4 v = __ldg(idx4 + i);
        const int b = i << 2;
        int4 nx;
        nx.x = atomicExch(&g_head[v.x], b + 1) - 1;
        nx.y = atomicExch(&g_head[v.y], b + 2) - 1;
        nx.z = atomicExch(&g_head[v.z], b + 3) - 1;
        nx.w = atomicExch(&g_head[v.w], b + 4) - 1;
        ((int4*)g_next)[i] = nx;
    }
    for (int i = (n4 << 2) + blockIdx.x * blockDim.x + threadIdx.x; i < N; i += stride)
        g_next[i] = atomicExch(&g_head[__ldg(idx + i)], i + 1) - 1;
}

// ---------------------------------------------------------------------------
// Fused gather + Adam update. One warp per vocab row, float4 per lane.
// Walk the row's linked list; next-pointer and grad loads issue back-to-back.
// Resets head[row] to 0 afterwards (self-restoring index for graph replay).
// ---------------------------------------------------------------------------
__global__ void __launch_bounds__(256, 7)
sadam_update_k(const float4* __restrict__ grad,
               const float4* __restrict__ emb,
               const float*  __restrict__ step_in,
               const float4* __restrict__ mem,
               const float4* __restrict__ pw,
               float4* __restrict__ out_emb,
               float*  __restrict__ out_step,
               float4* __restrict__ out_mem,
               float4* __restrict__ out_pow,
               int V) {
    const unsigned gtid = blockIdx.x * blockDim.x + threadIdx.x;
    const unsigned row  = gtid >> 5;
    if (row >= (unsigned)V) return;
    const unsigned lane = gtid & 31u;
    const unsigned i4   = row * (DD / 4) + lane;   // < 2^25, fits 32-bit

    // Start the dependent gather chain first.
    int r = __ldg(&g_head[row]) - 1;      // -1 if untouched (lane-uniform)

    // Independent streams overlap the chain.
    float4 e = __ldcs(emb + i4);
    float4 m = __ldcs(mem + i4);
    float4 p = __ldcs(pw  + i4);
    const float st = __ldg(step_in + row);

    float4 ne, nm, np;
    float  nstep;

    if (r >= 0) {
        // Reset index for the next graph replay (this warp owns the row).
        if (lane == 0) g_head[row] = 0;

        float4 gs = make_float4(0.f, 0.f, 0.f, 0.f);
        int cnt = 0;
        do {
            const int rn = __ldg(&g_next[r]);            // issues with grad load
            float4 g = __ldcs(grad + (unsigned)r * (DD / 4) + lane);
            gs.x += g.x; gs.y += g.y; gs.z += g.z; gs.w += g.w;
            cnt++;
            r = rn;
        } while (r >= 0);

        nstep = st + 1.f;
        const float inv = 1.f / (float)cnt;
        const float d1 = 1.f - exp2f(nstep * -0.15200309344504997f);   // 1-0.9^s
        const float d2 = 1.f - exp2f(nstep * -0.0014434169010128458f); // 1-0.999^s
        const float c1  = 0.001f / d1;
        const float id2 = 1.f / d2;

        #define ADAM1(GS, M, P, E, NM, NP, NE)                       \
        {                                                             \
            float g = (GS) * inv;                                     \
            NM = 0.9f * (M) + 0.1f * g;                               \
            NP = 0.999f * (P) + 0.001f * (g * g);                     \
            float stdv = c1 * NM / (sqrtf(NP * id2) + 1e-8f);         \
            NE = (E) - stdv;                                          \
        }
        ADAM1(gs.x, m.x, p.x, e.x, nm.x, np.x, ne.x)
        ADAM1(gs.y, m.y, p.y, e.y, nm.y, np.y, ne.y)
        ADAM1(gs.z, m.z, p.z, e.z, nm.z, np.z, ne.z)
        ADAM1(gs.w, m.w, p.w, e.w, nm.w, np.w, ne.w)
        #undef ADAM1
    } else {
        nstep = st;
        ne = e; nm = m; np = p;
    }

    __stcs(out_emb + i4, ne);
    __stcs(out_mem + i4, nm);
    __stcs(out_pow + i4, np);
    if (lane == 0) out_step[row] = nstep;
}

// ---------------------------------------------------------------------------
extern "C" void kernel_launch(void* const* d_in, const int* in_sizes, int n_in,
                              void* d_out, int out_size) {
    const int*   idx  = (const int*)  d_in[0];
    const float* grad = (const float*)d_in[1];
    const float* emb  = (const float*)d_in[2];
    const float* step = (const float*)d_in[3];
    const float* mem  = (const float*)d_in[4];
    const float* pw   = (const float*)d_in[5];

    const int N = in_sizes[0];
    const int V = in_sizes[3];

    float* out      = (float*)d_out;
    float* out_emb  = out;
    float* out_step = out_emb + (long)V * DD;
    float* out_mem  = out_step + V;
    float* out_pow  = out_mem + (long)V * DD;

    link_k<<<592, 256>>>(idx, N);

    {
        const long threads = (long)V * 32;
        const int  blocks  = (int)((threads + 255) / 256);
        sadam_update_k<<<blocks, 256>>>((const float4*)grad, (const float4*)emb,
                                        step, (const float4*)mem, (const float4*)pw,
                                        (float4*)out_emb, out_step,
                                        (float4*)out_mem, (float4*)out_pow, V);
    }
}